// round 12
// baseline (speedup 1.0000x reference)
#include <cuda_runtime.h>
#include <cuda_fp16.h>

// Problem constants (fixed by the dataset)
#define NMAX 100000
#define EMAX 1600000
#define D    64
#define G    64

// ---- device scratch (no allocations allowed) ----
__device__ int   g_degi  [NMAX];        // in-degree (real edges only)
__device__ float g_dinv  [NMAX];        // rsqrt(deg+1)
__device__ int   g_off   [NMAX + 1];    // CSR row offsets (by destination)
__device__ int   g_cursor[NMAX];        // build cursors
__device__ int   g_bsum  [256];         // scan block partials
__device__ int   g_csrc  [EMAX];        // CSR: source node per edge slot
__device__ float g_bufA  [NMAX * D];
__device__ __half2 g_hs  [NMAX * D / 2];  // hs = (x@W)*dinv, fp16 storage
__device__ float g_bufC  [NMAX * D];
__device__ float g_pool  [G * D];
__device__ float g_cnt   [G];

// ------------------------------------------------------------------
// K_hist: in-degree histogram over edge targets (col)
// ------------------------------------------------------------------
__global__ void k_hist(const int* __restrict__ col, int E) {
    int e = blockIdx.x * blockDim.x + threadIdx.x;
    if (e < E) atomicAdd(&g_degi[col[e]], 1);
}

// ------------------------------------------------------------------
// Scan pass 1: per-block (1024 elems) exclusive scan of g_degi -> g_off,
//              block totals -> g_bsum. Also computes dinv = rsqrt(deg+1).
// ------------------------------------------------------------------
__global__ void k_scan1(int N) {
    __shared__ int sh[256];
    int t = threadIdx.x;
    int base = blockIdx.x * 1024;
    int v[4];
    int sum = 0;
#pragma unroll
    for (int j = 0; j < 4; j++) {
        int idx = base + t * 4 + j;
        v[j] = (idx < N) ? g_degi[idx] : 0;
        if (idx < N) g_dinv[idx] = rsqrtf((float)(v[j] + 1));
        sum += v[j];
    }
    sh[t] = sum;
    __syncthreads();
    for (int o = 1; o < 256; o <<= 1) {
        int x = (t >= o) ? sh[t - o] : 0;
        __syncthreads();
        sh[t] += x;
        __syncthreads();
    }
    int excl = sh[t] - sum;
    if (t == 255) g_bsum[blockIdx.x] = sh[255];
    int run = excl;
#pragma unroll
    for (int j = 0; j < 4; j++) {
        int idx = base + t * 4 + j;
        if (idx < N) g_off[idx] = run;
        run += v[j];
    }
}

// ------------------------------------------------------------------
// Scan pass 2: single block exclusive-scans the block partials (B <= 256)
// ------------------------------------------------------------------
__global__ void k_scan2(int B) {
    __shared__ int sh[256];
    int t = threadIdx.x;
    int v = (t < B) ? g_bsum[t] : 0;
    sh[t] = v;
    __syncthreads();
    for (int o = 1; o < 256; o <<= 1) {
        int x = (t >= o) ? sh[t - o] : 0;
        __syncthreads();
        sh[t] += x;
        __syncthreads();
    }
    if (t < B) g_bsum[t] = sh[t] - v;
}

// ------------------------------------------------------------------
// Scan pass 3: add block base, init cursors, set sentinel off[N]=E
// ------------------------------------------------------------------
__global__ void k_scan3(int N, int E) {
    int i = blockIdx.x * blockDim.x + threadIdx.x;
    if (i < N) {
        int o = g_off[i] + g_bsum[i >> 10];
        g_off[i]    = o;
        g_cursor[i] = o;
    }
    if (i == 0) g_off[N] = E;
}

// ------------------------------------------------------------------
// K_build: fill CSR source array via per-destination cursors
// ------------------------------------------------------------------
__global__ void k_build(const int* __restrict__ row, const int* __restrict__ col, int E) {
    int e = blockIdx.x * blockDim.x + threadIdx.x;
    if (e < E) {
        int p = atomicAdd(&g_cursor[col[e]], 1);
        g_csrc[p] = row[e];
    }
}

// ------------------------------------------------------------------
// K_mm v4: hs = fp16( (relu?(x) @ W) * dinv )
//   256 threads = 16 row-groups x 16 col-quads; thread computes 8 rows x 4 cols
//   (128 rows/block). Per kq: 4 W LDS.128 + 8 x LDS.128 per 128 FFMA.
//   If nt != nullptr, x row = emb_table[nt[n]] (fused embedding gather).
// ------------------------------------------------------------------
__global__ void __launch_bounds__(256)
k_mm(const float* __restrict__ x, const int* __restrict__ nt,
     const float* __restrict__ emb,
     const float* __restrict__ W,
     __half2* __restrict__ hs,
     int N, int relu_in) {
    __shared__ float4 sW4[D * 16];       // [k][dq]      16 KB
    __shared__ float4 sx4[128 * 16];     // [row][kq]    32 KB
    int tid = threadIdx.x;
    const float4* W4 = (const float4*)W;
    for (int i = tid; i < D * 16; i += 256) sW4[i] = W4[i];

    int base = blockIdx.x * 128;
    for (int t4 = tid; t4 < 128 * 16; t4 += 256) {
        int r  = t4 >> 4;
        int kq = t4 & 15;
        int n  = base + r;
        float4 v = make_float4(0.f, 0.f, 0.f, 0.f);
        if (n < N) {
            const float4* src = nt ? ((const float4*)emb + (long long)nt[n] * 16)
                                   : ((const float4*)x + (long long)n * 16);
            v = src[kq];
            if (relu_in) {
                v.x = fmaxf(v.x, 0.f); v.y = fmaxf(v.y, 0.f);
                v.z = fmaxf(v.z, 0.f); v.w = fmaxf(v.w, 0.f);
            }
        }
        sx4[t4] = v;
    }
    __syncthreads();

    int dq = tid & 15;     // column quad 0..15
    int rg = tid >> 4;     // row group 0..15 -> rows rg*8 .. rg*8+7
    int n0 = base + rg * 8;

    float4 a[8];
#pragma unroll
    for (int r = 0; r < 8; r++) a[r] = make_float4(0.f, 0.f, 0.f, 0.f);

#pragma unroll
    for (int kq = 0; kq < 16; kq++) {
        float4 w0 = sW4[(kq * 4 + 0) * 16 + dq];
        float4 w1 = sW4[(kq * 4 + 1) * 16 + dq];
        float4 w2 = sW4[(kq * 4 + 2) * 16 + dq];
        float4 w3 = sW4[(kq * 4 + 3) * 16 + dq];
#pragma unroll
        for (int r = 0; r < 8; r++) {
            float4 xv = sx4[(rg * 8 + r) * 16 + kq];
            a[r].x = fmaf(xv.x, w0.x, a[r].x); a[r].y = fmaf(xv.x, w0.y, a[r].y);
            a[r].z = fmaf(xv.x, w0.z, a[r].z); a[r].w = fmaf(xv.x, w0.w, a[r].w);
            a[r].x = fmaf(xv.y, w1.x, a[r].x); a[r].y = fmaf(xv.y, w1.y, a[r].y);
            a[r].z = fmaf(xv.y, w1.z, a[r].z); a[r].w = fmaf(xv.y, w1.w, a[r].w);
            a[r].x = fmaf(xv.z, w2.x, a[r].x); a[r].y = fmaf(xv.z, w2.y, a[r].y);
            a[r].z = fmaf(xv.z, w2.z, a[r].z); a[r].w = fmaf(xv.z, w2.w, a[r].w);
            a[r].x = fmaf(xv.w, w3.x, a[r].x); a[r].y = fmaf(xv.w, w3.y, a[r].y);
            a[r].z = fmaf(xv.w, w3.z, a[r].z); a[r].w = fmaf(xv.w, w3.w, a[r].w);
        }
    }

    uint2* H2 = (uint2*)hs;
#pragma unroll
    for (int r = 0; r < 8; r++) {
        int n = n0 + r;
        if (n < N) {
            float di = g_dinv[n];
            __half2 h0 = __floats2half2_rn(a[r].x * di, a[r].y * di);
            __half2 h1 = __floats2half2_rn(a[r].z * di, a[r].w * di);
            uint2 st;
            st.x = *(unsigned int*)&h0;
            st.y = *(unsigned int*)&h1;
            H2[(long long)n * 16 + dq] = st;
        }
    }
}

// ------------------------------------------------------------------
// K_agg v4: y[n] = b + dinv[n] * ( sum_{src in in(n)} hs[src] + hs[n] )
//   warp per node, ONE half2 per lane (128B/row gather, 1 wavefront/edge);
//   fp32 accumulation, 8/4/1 laddered unroll, 4 accumulator chains.
// ------------------------------------------------------------------
__global__ void __launch_bounds__(256)
k_agg(const __half2* __restrict__ hs, const float* __restrict__ b,
      float* __restrict__ y, int N) {
    int w    = (blockIdx.x * blockDim.x + threadIdx.x) >> 5;
    int lane = threadIdx.x & 31;
    if (w >= N) return;
    int i   = g_off[w];
    int end = g_off[w + 1];

    // hoist epilogue operands so their latency overlaps the gather loop
    float2 hv = __half22float2(hs[(long long)w * 32 + lane]);
    float  di = g_dinv[w];
    float  bx = b[lane * 2];
    float  by = b[lane * 2 + 1];

    float ax0 = 0.f, ay0 = 0.f, ax1 = 0.f, ay1 = 0.f;
    float ax2 = 0.f, ay2 = 0.f, ax3 = 0.f, ay3 = 0.f;

    for (; i + 7 < end; i += 8) {
        int s0 = __ldg(&g_csrc[i]);
        int s1 = __ldg(&g_csrc[i + 1]);
        int s2 = __ldg(&g_csrc[i + 2]);
        int s3 = __ldg(&g_csrc[i + 3]);
        int s4 = __ldg(&g_csrc[i + 4]);
        int s5 = __ldg(&g_csrc[i + 5]);
        int s6 = __ldg(&g_csrc[i + 6]);
        int s7 = __ldg(&g_csrc[i + 7]);
        float2 v0 = __half22float2(hs[(long long)s0 * 32 + lane]);
        float2 v1 = __half22float2(hs[(long long)s1 * 32 + lane]);
        float2 v2 = __half22float2(hs[(long long)s2 * 32 + lane]);
        float2 v3 = __half22float2(hs[(long long)s3 * 32 + lane]);
        float2 v4 = __half22float2(hs[(long long)s4 * 32 + lane]);
        float2 v5 = __half22float2(hs[(long long)s5 * 32 + lane]);
        float2 v6 = __half22float2(hs[(long long)s6 * 32 + lane]);
        float2 v7 = __half22float2(hs[(long long)s7 * 32 + lane]);
        ax0 += v0.x + v1.x;  ay0 += v0.y + v1.y;
        ax1 += v2.x + v3.x;  ay1 += v2.y + v3.y;
        ax2 += v4.x + v5.x;  ay2 += v4.y + v5.y;
        ax3 += v6.x + v7.x;  ay3 += v6.y + v7.y;
    }
    for (; i + 3 < end; i += 4) {
        int s0 = __ldg(&g_csrc[i]);
        int s1 = __ldg(&g_csrc[i + 1]);
        int s2 = __ldg(&g_csrc[i + 2]);
        int s3 = __ldg(&g_csrc[i + 3]);
        float2 v0 = __half22float2(hs[(long long)s0 * 32 + lane]);
        float2 v1 = __half22float2(hs[(long long)s1 * 32 + lane]);
        float2 v2 = __half22float2(hs[(long long)s2 * 32 + lane]);
        float2 v3 = __half22float2(hs[(long long)s3 * 32 + lane]);
        ax0 += v0.x + v1.x;  ay0 += v0.y + v1.y;
        ax1 += v2.x + v3.x;  ay1 += v2.y + v3.y;
    }
    for (; i < end; i++) {
        int s = __ldg(&g_csrc[i]);
        float2 v = __half22float2(hs[(long long)s * 32 + lane]);
        ax2 += v.x;  ay2 += v.y;
    }

    float2 o;
    o.x = bx + di * ((ax0 + ax1) + (ax2 + ax3) + hv.x);
    o.y = by + di * ((ay0 + ay1) + (ay2 + ay3) + hv.y);
    ((float2*)y)[(long long)w * 32 + lane] = o;
}

// ------------------------------------------------------------------
// K_pool: segment mean accumulation (batch is sorted -> register-accumulate,
//         flush to global on graph change). 64 threads/block.
// ------------------------------------------------------------------
#define POOL_CHUNK 256
__global__ void k_pool(const float* __restrict__ x, const int* __restrict__ batch, int N) {
    int d = threadIdx.x;              // 0..63
    int s = blockIdx.x * POOL_CHUNK;
    int eN = min(s + POOL_CHUNK, N);
    float acc = 0.0f, cnt = 0.0f;
    int cur = -1;
    for (int n = s; n < eN; n++) {
        int bg = batch[n];
        if (bg != cur) {
            if (cur >= 0) {
                atomicAdd(&g_pool[cur * D + d], acc);
                if (d == 0) atomicAdd(&g_cnt[cur], cnt);
            }
            cur = bg; acc = 0.0f; cnt = 0.0f;
        }
        acc += x[n * D + d];
        cnt += 1.0f;
    }
    if (cur >= 0) {
        atomicAdd(&g_pool[cur * D + d], acc);
        if (d == 0) atomicAdd(&g_cnt[cur], cnt);
    }
}

// ------------------------------------------------------------------
// K_final: pooled = sum/max(cnt,1); out = pooled / ||pooled||_2
// ------------------------------------------------------------------
__global__ void k_final(float* __restrict__ out) {
    int r    = blockIdx.x * 32 + (threadIdx.x >> 5);
    int lane = threadIdx.x & 31;
    float c  = fmaxf(g_cnt[r], 1.0f);
    float v0 = g_pool[r * D + lane]      / c;
    float v1 = g_pool[r * D + 32 + lane] / c;
    float ss = v0 * v0 + v1 * v1;
#pragma unroll
    for (int o = 16; o > 0; o >>= 1) ss += __shfl_xor_sync(0xFFFFFFFFu, ss, o);
    float inv = rsqrtf(ss);
    out[r * D + lane]      = v0 * inv;
    out[r * D + 32 + lane] = v1 * inv;
}

// ------------------------------------------------------------------
// Host launcher
// ------------------------------------------------------------------
extern "C" void kernel_launch(void* const* d_in, const int* in_sizes, int n_in,
                              void* d_out, int out_size) {
    const int*   node_types = (const int*)  d_in[0];
    const int*   edge_index = (const int*)  d_in[1];
    const int*   batch      = (const int*)  d_in[2];
    const float* emb_table  = (const float*)d_in[3];
    const float* W1 = (const float*)d_in[4];
    const float* b1 = (const float*)d_in[5];
    const float* W2 = (const float*)d_in[6];
    const float* b2 = (const float*)d_in[7];
    const float* W3 = (const float*)d_in[8];
    const float* b3 = (const float*)d_in[9];
    float* out = (float*)d_out;

    const int N = in_sizes[0];
    const int E = in_sizes[1] / 2;
    const int* row = edge_index;        // edge_index[0, :]
    const int* col = edge_index + E;    // edge_index[1, :]

    float*   bufA; cudaGetSymbolAddress((void**)&bufA, g_bufA);
    __half2* hsB;  cudaGetSymbolAddress((void**)&hsB,  g_hs);
    float*   bufC; cudaGetSymbolAddress((void**)&bufC, g_bufC);
    int*     degi; cudaGetSymbolAddress((void**)&degi, g_degi);
    float*   pool; cudaGetSymbolAddress((void**)&pool, g_pool);
    float*   cnt;  cudaGetSymbolAddress((void**)&cnt,  g_cnt);

    const int T = 256;
    const int scanB = (N + 1023) / 1024;

    cudaMemsetAsync(degi, 0, N * sizeof(int));
    cudaMemsetAsync(pool, 0, G * D * sizeof(float));
    cudaMemsetAsync(cnt,  0, G * sizeof(float));

    int mm_blocks  = (N + 127) / 128;
    int agg_blocks = (N + 7) / 8;       // 8 warps/block, warp per node

    // ---- precompute + layer-1 mm interleaved so mm1 is the 4th kernel (-> ncu)
    k_hist <<<(E + T - 1) / T, T>>>(col, E);                              // 1
    k_scan1<<<scanB, 256>>>(N);                                           // 2
    k_scan2<<<1, 256>>>(scanB);                                           // 3
    k_mm   <<<mm_blocks, T>>>(nullptr, node_types, emb_table, W1, hsB, N, 0); // 4 <- profiled
    k_scan3<<<(N + T - 1) / T, T>>>(N, E);                                // 5
    k_build<<<(E + T - 1) / T, T>>>(row, col, E);                         // 6

    // layer 1 aggregation
    k_agg<<<agg_blocks, T>>>(hsB, b1, bufC, N);
    // layer 2
    k_mm <<<mm_blocks, T>>>(bufC, nullptr, nullptr, W2, hsB, N, 1);
    k_agg<<<agg_blocks, T>>>(hsB, b2, bufA, N);
    // layer 3
    k_mm <<<mm_blocks, T>>>(bufA, nullptr, nullptr, W3, hsB, N, 1);
    k_agg<<<agg_blocks, T>>>(hsB, b3, bufC, N);

    // mean-pool + L2 normalize
    k_pool <<<(N + POOL_CHUNK - 1) / POOL_CHUNK, 64>>>(bufC, batch, N);
    k_final<<<2, 1024>>>(out);
}

// round 14
// speedup vs baseline: 1.4068x; 1.4068x over previous
#include <cuda_runtime.h>
#include <cuda_fp16.h>

// Problem constants (fixed by the dataset)
#define NMAX 100000
#define EMAX 1600000
#define D    64
#define G    64

// ---- device scratch (no allocations allowed) ----
__device__ int   g_degi  [NMAX];        // in-degree (real edges only)
__device__ float g_dinv  [NMAX];        // rsqrt(deg+1)
__device__ int   g_off   [NMAX + 1];    // CSR row offsets (by destination)
__device__ int   g_cursor[NMAX];        // build cursors
__device__ int   g_bsum  [256];         // scan block partials
__device__ int   g_csrc  [EMAX];        // CSR: source node per edge slot
__device__ float g_bufA  [NMAX * D];
__device__ uint4 g_hs    [NMAX * 8];    // hs = (x@W)*dinv, fp16 (64 halves = 8 uint4 / row)
__device__ float g_bufC  [NMAX * D];
__device__ float g_pool  [G * D];
__device__ float g_cnt   [G];

// ------------------------------------------------------------------
// K_hist: in-degree histogram over edge targets (col)
// ------------------------------------------------------------------
__global__ void k_hist(const int* __restrict__ col, int E) {
    int e = blockIdx.x * blockDim.x + threadIdx.x;
    if (e < E) atomicAdd(&g_degi[col[e]], 1);
}

// ------------------------------------------------------------------
// Scan pass 1: per-block (1024 elems) exclusive scan of g_degi -> g_off,
//              block totals -> g_bsum. Also computes dinv = rsqrt(deg+1).
// ------------------------------------------------------------------
__global__ void k_scan1(int N) {
    __shared__ int sh[256];
    int t = threadIdx.x;
    int base = blockIdx.x * 1024;
    int v[4];
    int sum = 0;
#pragma unroll
    for (int j = 0; j < 4; j++) {
        int idx = base + t * 4 + j;
        v[j] = (idx < N) ? g_degi[idx] : 0;
        if (idx < N) g_dinv[idx] = rsqrtf((float)(v[j] + 1));
        sum += v[j];
    }
    sh[t] = sum;
    __syncthreads();
    for (int o = 1; o < 256; o <<= 1) {
        int x = (t >= o) ? sh[t - o] : 0;
        __syncthreads();
        sh[t] += x;
        __syncthreads();
    }
    int excl = sh[t] - sum;
    if (t == 255) g_bsum[blockIdx.x] = sh[255];
    int run = excl;
#pragma unroll
    for (int j = 0; j < 4; j++) {
        int idx = base + t * 4 + j;
        if (idx < N) g_off[idx] = run;
        run += v[j];
    }
}

// ------------------------------------------------------------------
// Scan pass 2: single block exclusive-scans the block partials (B <= 256)
// ------------------------------------------------------------------
__global__ void k_scan2(int B) {
    __shared__ int sh[256];
    int t = threadIdx.x;
    int v = (t < B) ? g_bsum[t] : 0;
    sh[t] = v;
    __syncthreads();
    for (int o = 1; o < 256; o <<= 1) {
        int x = (t >= o) ? sh[t - o] : 0;
        __syncthreads();
        sh[t] += x;
        __syncthreads();
    }
    if (t < B) g_bsum[t] = sh[t] - v;
}

// ------------------------------------------------------------------
// Scan pass 3: add block base, init cursors, set sentinel off[N]=E
// ------------------------------------------------------------------
__global__ void k_scan3(int N, int E) {
    int i = blockIdx.x * blockDim.x + threadIdx.x;
    if (i < N) {
        int o = g_off[i] + g_bsum[i >> 10];
        g_off[i]    = o;
        g_cursor[i] = o;
    }
    if (i == 0) g_off[N] = E;
}

// ------------------------------------------------------------------
// K_build: fill CSR source array via per-destination cursors
// ------------------------------------------------------------------
__global__ void k_build(const int* __restrict__ row, const int* __restrict__ col, int E) {
    int e = blockIdx.x * blockDim.x + threadIdx.x;
    if (e < E) {
        int p = atomicAdd(&g_cursor[col[e]], 1);
        g_csrc[p] = row[e];
    }
}

// ------------------------------------------------------------------
// K_mm v4: hs = fp16( (relu?(x) @ W) * dinv )
//   256 threads = 16 row-groups x 16 col-quads; thread computes 8 rows x 4 cols
//   (128 rows/block).
//   If nt != nullptr, x row = emb_table[nt[n]] (fused embedding gather).
// ------------------------------------------------------------------
__global__ void __launch_bounds__(256)
k_mm(const float* __restrict__ x, const int* __restrict__ nt,
     const float* __restrict__ emb,
     const float* __restrict__ W,
     uint2* __restrict__ hs,
     int N, int relu_in) {
    __shared__ float4 sW4[D * 16];       // [k][dq]      16 KB
    __shared__ float4 sx4[128 * 16];     // [row][kq]    32 KB
    int tid = threadIdx.x;
    const float4* W4 = (const float4*)W;
    for (int i = tid; i < D * 16; i += 256) sW4[i] = W4[i];

    int base = blockIdx.x * 128;
    for (int t4 = tid; t4 < 128 * 16; t4 += 256) {
        int r  = t4 >> 4;
        int kq = t4 & 15;
        int n  = base + r;
        float4 v = make_float4(0.f, 0.f, 0.f, 0.f);
        if (n < N) {
            const float4* src = nt ? ((const float4*)emb + (long long)nt[n] * 16)
                                   : ((const float4*)x + (long long)n * 16);
            v = src[kq];
            if (relu_in) {
                v.x = fmaxf(v.x, 0.f); v.y = fmaxf(v.y, 0.f);
                v.z = fmaxf(v.z, 0.f); v.w = fmaxf(v.w, 0.f);
            }
        }
        sx4[t4] = v;
    }
    __syncthreads();

    int dq = tid & 15;     // column quad 0..15
    int rg = tid >> 4;     // row group 0..15 -> rows rg*8 .. rg*8+7
    int n0 = base + rg * 8;

    float4 a[8];
#pragma unroll
    for (int r = 0; r < 8; r++) a[r] = make_float4(0.f, 0.f, 0.f, 0.f);

#pragma unroll
    for (int kq = 0; kq < 16; kq++) {
        float4 w0 = sW4[(kq * 4 + 0) * 16 + dq];
        float4 w1 = sW4[(kq * 4 + 1) * 16 + dq];
        float4 w2 = sW4[(kq * 4 + 2) * 16 + dq];
        float4 w3 = sW4[(kq * 4 + 3) * 16 + dq];
#pragma unroll
        for (int r = 0; r < 8; r++) {
            float4 xv = sx4[(rg * 8 + r) * 16 + kq];
            a[r].x = fmaf(xv.x, w0.x, a[r].x); a[r].y = fmaf(xv.x, w0.y, a[r].y);
            a[r].z = fmaf(xv.x, w0.z, a[r].z); a[r].w = fmaf(xv.x, w0.w, a[r].w);
            a[r].x = fmaf(xv.y, w1.x, a[r].x); a[r].y = fmaf(xv.y, w1.y, a[r].y);
            a[r].z = fmaf(xv.y, w1.z, a[r].z); a[r].w = fmaf(xv.y, w1.w, a[r].w);
            a[r].x = fmaf(xv.z, w2.x, a[r].x); a[r].y = fmaf(xv.z, w2.y, a[r].y);
            a[r].z = fmaf(xv.z, w2.z, a[r].z); a[r].w = fmaf(xv.z, w2.w, a[r].w);
            a[r].x = fmaf(xv.w, w3.x, a[r].x); a[r].y = fmaf(xv.w, w3.y, a[r].y);
            a[r].z = fmaf(xv.w, w3.z, a[r].z); a[r].w = fmaf(xv.w, w3.w, a[r].w);
        }
    }

#pragma unroll
    for (int r = 0; r < 8; r++) {
        int n = n0 + r;
        if (n < N) {
            float di = g_dinv[n];
            __half2 h0 = __floats2half2_rn(a[r].x * di, a[r].y * di);
            __half2 h1 = __floats2half2_rn(a[r].z * di, a[r].w * di);
            uint2 st;
            st.x = *(unsigned int*)&h0;
            st.y = *(unsigned int*)&h1;
            hs[(long long)n * 16 + dq] = st;
        }
    }
}

// ------------------------------------------------------------------
// K_agg v5: y[n] = b + dinv[n] * ( sum_{src in in(n)} hs[src] + hs[n] )
//   warp per node, 8 lanes per edge: lane (g = lane>>3, sub = lane&7)
//   loads uint4 = 8 fp16 dims -> 4 edges per gather instruction.
//   HADD2 pairwise (2 values per fp16 partial) + fp32 accumulate.
//   Shfl butterfly combines the 4 edge-groups; lanes 0..15 store float4.
// ------------------------------------------------------------------
__global__ void __launch_bounds__(256)
k_agg(const uint4* __restrict__ hs, const float* __restrict__ b,
      float* __restrict__ y, int N) {
    int w    = (blockIdx.x * blockDim.x + threadIdx.x) >> 5;
    int lane = threadIdx.x & 31;
    if (w >= N) return;
    int g   = lane >> 3;     // edge sub-group 0..3
    int sub = lane & 7;      // 16B chunk within row: dims [8*sub, 8*sub+8)

    int i   = g_off[w];
    int end = g_off[w + 1];

    float di   = g_dinv[w];
    uint4 self = hs[(long long)w * 8 + sub];

    float acc[8];
#pragma unroll
    for (int k = 0; k < 8; k++) acc[k] = 0.f;

    // main loop: 8 edges per iteration (2 per group)
    for (; i + 8 <= end; i += 8) {
        int s0 = __ldg(&g_csrc[i + g]);
        int s1 = __ldg(&g_csrc[i + 4 + g]);
        uint4 p0 = hs[(long long)s0 * 8 + sub];
        uint4 p1 = hs[(long long)s1 * 8 + sub];
        __half2 t0 = __hadd2(*(__half2*)&p0.x, *(__half2*)&p1.x);
        __half2 t1 = __hadd2(*(__half2*)&p0.y, *(__half2*)&p1.y);
        __half2 t2 = __hadd2(*(__half2*)&p0.z, *(__half2*)&p1.z);
        __half2 t3 = __hadd2(*(__half2*)&p0.w, *(__half2*)&p1.w);
        float2 f;
        f = __half22float2(t0); acc[0] += f.x; acc[1] += f.y;
        f = __half22float2(t1); acc[2] += f.x; acc[3] += f.y;
        f = __half22float2(t2); acc[4] += f.x; acc[5] += f.y;
        f = __half22float2(t3); acc[6] += f.x; acc[7] += f.y;
    }
    // tail: up to 7 edges, 4 at a time, predicated per group
    for (; i < end; i += 4) {
        int idx = i + g;
        if (idx < end) {
            int s = __ldg(&g_csrc[idx]);
            uint4 p = hs[(long long)s * 8 + sub];
            float2 f;
            f = __half22float2(*(__half2*)&p.x); acc[0] += f.x; acc[1] += f.y;
            f = __half22float2(*(__half2*)&p.y); acc[2] += f.x; acc[3] += f.y;
            f = __half22float2(*(__half2*)&p.z); acc[4] += f.x; acc[5] += f.y;
            f = __half22float2(*(__half2*)&p.w); acc[6] += f.x; acc[7] += f.y;
        }
    }

    // combine the 4 edge-groups (lanes sharing the same sub)
#pragma unroll
    for (int k = 0; k < 8; k++) {
        acc[k] += __shfl_xor_sync(0xFFFFFFFFu, acc[k], 8);
        acc[k] += __shfl_xor_sync(0xFFFFFFFFu, acc[k], 16);
    }

    // add self-loop term (post-butterfly so it is counted once)
    {
        float2 f;
        f = __half22float2(*(__half2*)&self.x); acc[0] += f.x; acc[1] += f.y;
        f = __half22float2(*(__half2*)&self.y); acc[2] += f.x; acc[3] += f.y;
        f = __half22float2(*(__half2*)&self.z); acc[4] += f.x; acc[5] += f.y;
        f = __half22float2(*(__half2*)&self.w); acc[6] += f.x; acc[7] += f.y;
    }

    // epilogue + store: groups 0 and 1 each write one float4
    if (g < 2) {
        float4 bv = ((const float4*)b)[sub * 2 + g];
        int k0 = g * 4;
        float4 o;
        o.x = bv.x + di * acc[k0 + 0];
        o.y = bv.y + di * acc[k0 + 1];
        o.z = bv.z + di * acc[k0 + 2];
        o.w = bv.w + di * acc[k0 + 3];
        ((float4*)y)[(long long)w * 16 + sub * 2 + g] = o;
    }
}

// ------------------------------------------------------------------
// K_pool v2: segment mean accumulation. CHUNK=32 nodes/block (42 warps/SM),
//   4-wide unrolled loads for MLP. batch sorted -> register-accumulate,
//   flush on graph change. 64 threads/block (thread = dim).
// ------------------------------------------------------------------
#define POOL_CHUNK 32

#define POOL_STEP(bg, v)                                    \
    do {                                                    \
        if ((bg) != cur) {                                  \
            if (cur >= 0) {                                 \
                atomicAdd(&g_pool[cur * D + d], acc);       \
                if (d == 0) atomicAdd(&g_cnt[cur], cnt);    \
            }                                               \
            cur = (bg); acc = 0.f; cnt = 0.f;               \
        }                                                   \
        acc += (v); cnt += 1.f;                             \
    } while (0)

__global__ void k_pool(const float* __restrict__ x, const int* __restrict__ batch, int N) {
    int d = threadIdx.x;              // 0..63
    int s = blockIdx.x * POOL_CHUNK;
    int eN = min(s + POOL_CHUNK, N);
    float acc = 0.0f, cnt = 0.0f;
    int cur = -1;
    int n = s;
    for (; n + 4 <= eN; n += 4) {
        int b0 = batch[n],     b1 = batch[n + 1];
        int b2 = batch[n + 2], b3 = batch[n + 3];
        float v0 = x[(long long)n * D + d];
        float v1 = x[(long long)(n + 1) * D + d];
        float v2 = x[(long long)(n + 2) * D + d];
        float v3 = x[(long long)(n + 3) * D + d];
        POOL_STEP(b0, v0);
        POOL_STEP(b1, v1);
        POOL_STEP(b2, v2);
        POOL_STEP(b3, v3);
    }
    for (; n < eN; n++) {
        int bg = batch[n];
        float v = x[(long long)n * D + d];
        POOL_STEP(bg, v);
    }
    if (cur >= 0) {
        atomicAdd(&g_pool[cur * D + d], acc);
        if (d == 0) atomicAdd(&g_cnt[cur], cnt);
    }
}

// ------------------------------------------------------------------
// K_final: pooled = sum/max(cnt,1); out = pooled / ||pooled||_2
// ------------------------------------------------------------------
__global__ void k_final(float* __restrict__ out) {
    int r    = blockIdx.x * 32 + (threadIdx.x >> 5);
    int lane = threadIdx.x & 31;
    float c  = fmaxf(g_cnt[r], 1.0f);
    float v0 = g_pool[r * D + lane]      / c;
    float v1 = g_pool[r * D + 32 + lane] / c;
    float ss = v0 * v0 + v1 * v1;
#pragma unroll
    for (int o = 16; o > 0; o >>= 1) ss += __shfl_xor_sync(0xFFFFFFFFu, ss, o);
    float inv = rsqrtf(ss);
    out[r * D + lane]      = v0 * inv;
    out[r * D + 32 + lane] = v1 * inv;
}

// ------------------------------------------------------------------
// Host launcher
// ------------------------------------------------------------------
extern "C" void kernel_launch(void* const* d_in, const int* in_sizes, int n_in,
                              void* d_out, int out_size) {
    const int*   node_types = (const int*)  d_in[0];
    const int*   edge_index = (const int*)  d_in[1];
    const int*   batch      = (const int*)  d_in[2];
    const float* emb_table  = (const float*)d_in[3];
    const float* W1 = (const float*)d_in[4];
    const float* b1 = (const float*)d_in[5];
    const float* W2 = (const float*)d_in[6];
    const float* b2 = (const float*)d_in[7];
    const float* W3 = (const float*)d_in[8];
    const float* b3 = (const float*)d_in[9];
    float* out = (float*)d_out;

    const int N = in_sizes[0];
    const int E = in_sizes[1] / 2;
    const int* row = edge_index;        // edge_index[0, :]
    const int* col = edge_index + E;    // edge_index[1, :]

    float* bufA; cudaGetSymbolAddress((void**)&bufA, g_bufA);
    uint4* hsB;  cudaGetSymbolAddress((void**)&hsB,  g_hs);
    float* bufC; cudaGetSymbolAddress((void**)&bufC, g_bufC);
    int*   degi; cudaGetSymbolAddress((void**)&degi, g_degi);
    float* pool; cudaGetSymbolAddress((void**)&pool, g_pool);
    float* cnt;  cudaGetSymbolAddress((void**)&cnt,  g_cnt);

    const int T = 256;
    const int scanB = (N + 1023) / 1024;

    cudaMemsetAsync(degi, 0, N * sizeof(int));
    cudaMemsetAsync(pool, 0, G * D * sizeof(float));
    cudaMemsetAsync(cnt,  0, G * sizeof(float));

    int mm_blocks  = (N + 127) / 128;
    int agg_blocks = (N + 7) / 8;       // 8 warps/block, warp per node

    // ---- precompute + layer-1 mm interleaved so mm1 is the 4th kernel (-> ncu)
    k_hist <<<(E + T - 1) / T, T>>>(col, E);                              // 1
    k_scan1<<<scanB, 256>>>(N);                                           // 2
    k_scan2<<<1, 256>>>(scanB);                                           // 3
    k_mm   <<<mm_blocks, T>>>(nullptr, node_types, emb_table, W1,
                              (uint2*)hsB, N, 0);                         // 4 <- profiled
    k_scan3<<<(N + T - 1) / T, T>>>(N, E);                                // 5
    k_build<<<(E + T - 1) / T, T>>>(row, col, E);                         // 6

    // layer 1 aggregation
    k_agg<<<agg_blocks, T>>>(hsB, b1, bufC, N);
    // layer 2
    k_mm <<<mm_blocks, T>>>(bufC, nullptr, nullptr, W2, (uint2*)hsB, N, 1);
    k_agg<<<agg_blocks, T>>>(hsB, b2, bufA, N);
    // layer 3
    k_mm <<<mm_blocks, T>>>(bufA, nullptr, nullptr, W3, (uint2*)hsB, N, 1);
    k_agg<<<agg_blocks, T>>>(hsB, b3, bufC, N);

    // mean-pool + L2 normalize
    k_pool <<<(N + POOL_CHUNK - 1) / POOL_CHUNK, 64>>>(bufC, batch, N);
    k_final<<<2, 1024>>>(out);
}

// round 15
// speedup vs baseline: 1.5203x; 1.0807x over previous
#include <cuda_runtime.h>
#include <cuda_fp16.h>

// Problem constants (fixed by the dataset)
#define NMAX 100000
#define EMAX 1600000
#define D    64
#define G    64
#define VMAX 64

// ---- device scratch (no allocations allowed) ----
__device__ int   g_degi  [NMAX];        // in-degree (real edges only)
__device__ float g_dinv  [NMAX];        // rsqrt(deg+1)
__device__ int   g_off   [NMAX + 1];    // CSR row offsets (by destination)
__device__ int   g_cursor[NMAX];        // build cursors
__device__ int   g_bsum  [256];         // scan block partials
__device__ int   g_csrc  [EMAX];        // CSR: source node per edge slot
__device__ float g_H1    [VMAX * D];    // H1 = emb_table @ W1 (V distinct rows)
__device__ float g_bufA  [NMAX * D];
__device__ uint4 g_hs    [NMAX * 8];    // hs = (x@W)*dinv, fp16 (64 halves = 8 uint4 / row)
__device__ float g_bufC  [NMAX * D];
__device__ float g_pool  [G * D];
__device__ float g_cnt   [G];

// ------------------------------------------------------------------
// K_htab: H1[v] = emb[v] @ W1   (V rows, tiny). One block per v, 64 threads.
// ------------------------------------------------------------------
__global__ void k_htab(const float* __restrict__ emb, const float* __restrict__ W) {
    int v = blockIdx.x;
    int d = threadIdx.x;
    __shared__ float se[D];
    se[d] = emb[v * D + d];
    __syncthreads();
    float acc = 0.0f;
#pragma unroll
    for (int k = 0; k < D; k++)
        acc = fmaf(se[k], W[k * D + d], acc);
    g_H1[v * D + d] = acc;
}

// ------------------------------------------------------------------
// K_hs1: layer-1 "matmul" via table: hs[n] = fp16( H1[nt[n]] * dinv[n] )
//   thread per uint2 (4 dims): i -> (n = i>>4, dq = i&15)
// ------------------------------------------------------------------
__global__ void __launch_bounds__(256)
k_hs1(const int* __restrict__ nt, uint2* __restrict__ hs, int N) {
    int i = blockIdx.x * blockDim.x + threadIdx.x;
    if (i >= N * 16) return;
    int n  = i >> 4;
    int dq = i & 15;
    int v  = nt[n];
    float di = g_dinv[n];
    float4 h = ((const float4*)g_H1)[v * 16 + dq];
    __half2 h0 = __floats2half2_rn(h.x * di, h.y * di);
    __half2 h1 = __floats2half2_rn(h.z * di, h.w * di);
    uint2 st;
    st.x = *(unsigned int*)&h0;
    st.y = *(unsigned int*)&h1;
    hs[(long long)n * 16 + dq] = st;
}

// ------------------------------------------------------------------
// K_hist: in-degree histogram over edge targets (col)
// ------------------------------------------------------------------
__global__ void k_hist(const int* __restrict__ col, int E) {
    int e = blockIdx.x * blockDim.x + threadIdx.x;
    if (e < E) atomicAdd(&g_degi[col[e]], 1);
}

// ------------------------------------------------------------------
// Scan pass 1: per-block (1024 elems) exclusive scan of g_degi -> g_off,
//              block totals -> g_bsum. Also computes dinv = rsqrt(deg+1).
// ------------------------------------------------------------------
__global__ void k_scan1(int N) {
    __shared__ int sh[256];
    int t = threadIdx.x;
    int base = blockIdx.x * 1024;
    int v[4];
    int sum = 0;
#pragma unroll
    for (int j = 0; j < 4; j++) {
        int idx = base + t * 4 + j;
        v[j] = (idx < N) ? g_degi[idx] : 0;
        if (idx < N) g_dinv[idx] = rsqrtf((float)(v[j] + 1));
        sum += v[j];
    }
    sh[t] = sum;
    __syncthreads();
    for (int o = 1; o < 256; o <<= 1) {
        int x = (t >= o) ? sh[t - o] : 0;
        __syncthreads();
        sh[t] += x;
        __syncthreads();
    }
    int excl = sh[t] - sum;
    if (t == 255) g_bsum[blockIdx.x] = sh[255];
    int run = excl;
#pragma unroll
    for (int j = 0; j < 4; j++) {
        int idx = base + t * 4 + j;
        if (idx < N) g_off[idx] = run;
        run += v[j];
    }
}

// ------------------------------------------------------------------
// Scan pass 2: single block exclusive-scans the block partials (B <= 256)
// ------------------------------------------------------------------
__global__ void k_scan2(int B) {
    __shared__ int sh[256];
    int t = threadIdx.x;
    int v = (t < B) ? g_bsum[t] : 0;
    sh[t] = v;
    __syncthreads();
    for (int o = 1; o < 256; o <<= 1) {
        int x = (t >= o) ? sh[t - o] : 0;
        __syncthreads();
        sh[t] += x;
        __syncthreads();
    }
    if (t < B) g_bsum[t] = sh[t] - v;
}

// ------------------------------------------------------------------
// Scan pass 3: add block base, init cursors, set sentinel off[N]=E
// ------------------------------------------------------------------
__global__ void k_scan3(int N, int E) {
    int i = blockIdx.x * blockDim.x + threadIdx.x;
    if (i < N) {
        int o = g_off[i] + g_bsum[i >> 10];
        g_off[i]    = o;
        g_cursor[i] = o;
    }
    if (i == 0) g_off[N] = E;
}

// ------------------------------------------------------------------
// K_build: fill CSR source array via per-destination cursors
// ------------------------------------------------------------------
__global__ void k_build(const int* __restrict__ row, const int* __restrict__ col, int E) {
    int e = blockIdx.x * blockDim.x + threadIdx.x;
    if (e < E) {
        int p = atomicAdd(&g_cursor[col[e]], 1);
        g_csrc[p] = row[e];
    }
}

// ------------------------------------------------------------------
// K_mm v4: hs = fp16( (relu?(x) @ W) * dinv )
//   256 threads = 16 row-groups x 16 col-quads; thread computes 8 rows x 4 cols
//   (128 rows/block).
// ------------------------------------------------------------------
__global__ void __launch_bounds__(256)
k_mm(const float* __restrict__ x,
     const float* __restrict__ W,
     uint2* __restrict__ hs,
     int N, int relu_in) {
    __shared__ float4 sW4[D * 16];       // [k][dq]      16 KB
    __shared__ float4 sx4[128 * 16];     // [row][kq]    32 KB
    int tid = threadIdx.x;
    const float4* W4 = (const float4*)W;
    for (int i = tid; i < D * 16; i += 256) sW4[i] = W4[i];

    int base = blockIdx.x * 128;
    for (int t4 = tid; t4 < 128 * 16; t4 += 256) {
        int r  = t4 >> 4;
        int kq = t4 & 15;
        int n  = base + r;
        float4 v = make_float4(0.f, 0.f, 0.f, 0.f);
        if (n < N) {
            v = ((const float4*)x)[(long long)n * 16 + kq];
            if (relu_in) {
                v.x = fmaxf(v.x, 0.f); v.y = fmaxf(v.y, 0.f);
                v.z = fmaxf(v.z, 0.f); v.w = fmaxf(v.w, 0.f);
            }
        }
        sx4[t4] = v;
    }
    __syncthreads();

    int dq = tid & 15;     // column quad 0..15
    int rg = tid >> 4;     // row group 0..15 -> rows rg*8 .. rg*8+7
    int n0 = base + rg * 8;

    float4 a[8];
#pragma unroll
    for (int r = 0; r < 8; r++) a[r] = make_float4(0.f, 0.f, 0.f, 0.f);

#pragma unroll
    for (int kq = 0; kq < 16; kq++) {
        float4 w0 = sW4[(kq * 4 + 0) * 16 + dq];
        float4 w1 = sW4[(kq * 4 + 1) * 16 + dq];
        float4 w2 = sW4[(kq * 4 + 2) * 16 + dq];
        float4 w3 = sW4[(kq * 4 + 3) * 16 + dq];
#pragma unroll
        for (int r = 0; r < 8; r++) {
            float4 xv = sx4[(rg * 8 + r) * 16 + kq];
            a[r].x = fmaf(xv.x, w0.x, a[r].x); a[r].y = fmaf(xv.x, w0.y, a[r].y);
            a[r].z = fmaf(xv.x, w0.z, a[r].z); a[r].w = fmaf(xv.x, w0.w, a[r].w);
            a[r].x = fmaf(xv.y, w1.x, a[r].x); a[r].y = fmaf(xv.y, w1.y, a[r].y);
            a[r].z = fmaf(xv.y, w1.z, a[r].z); a[r].w = fmaf(xv.y, w1.w, a[r].w);
            a[r].x = fmaf(xv.z, w2.x, a[r].x); a[r].y = fmaf(xv.z, w2.y, a[r].y);
            a[r].z = fmaf(xv.z, w2.z, a[r].z); a[r].w = fmaf(xv.z, w2.w, a[r].w);
            a[r].x = fmaf(xv.w, w3.x, a[r].x); a[r].y = fmaf(xv.w, w3.y, a[r].y);
            a[r].z = fmaf(xv.w, w3.z, a[r].z); a[r].w = fmaf(xv.w, w3.w, a[r].w);
        }
    }

#pragma unroll
    for (int r = 0; r < 8; r++) {
        int n = n0 + r;
        if (n < N) {
            float di = g_dinv[n];
            __half2 h0 = __floats2half2_rn(a[r].x * di, a[r].y * di);
            __half2 h1 = __floats2half2_rn(a[r].z * di, a[r].w * di);
            uint2 st;
            st.x = *(unsigned int*)&h0;
            st.y = *(unsigned int*)&h1;
            hs[(long long)n * 16 + dq] = st;
        }
    }
}

// ------------------------------------------------------------------
// K_agg v5: y[n] = b + dinv[n] * ( sum_{src in in(n)} hs[src] + hs[n] )
//   warp per node, 8 lanes per edge: lane (g = lane>>3, sub = lane&7)
//   loads uint4 = 8 fp16 dims -> 4 edges per gather instruction.
//   HADD2 pairwise + fp32 accumulate; shfl butterfly; float4 stores.
// ------------------------------------------------------------------
__global__ void __launch_bounds__(256)
k_agg(const uint4* __restrict__ hs, const float* __restrict__ b,
      float* __restrict__ y, int N) {
    int w    = (blockIdx.x * blockDim.x + threadIdx.x) >> 5;
    int lane = threadIdx.x & 31;
    if (w >= N) return;
    int g   = lane >> 3;     // edge sub-group 0..3
    int sub = lane & 7;      // 16B chunk within row: dims [8*sub, 8*sub+8)

    int i   = g_off[w];
    int end = g_off[w + 1];

    float di   = g_dinv[w];
    uint4 self = hs[(long long)w * 8 + sub];

    float acc[8];
#pragma unroll
    for (int k = 0; k < 8; k++) acc[k] = 0.f;

    // main loop: 8 edges per iteration (2 per group)
    for (; i + 8 <= end; i += 8) {
        int s0 = __ldg(&g_csrc[i + g]);
        int s1 = __ldg(&g_csrc[i + 4 + g]);
        uint4 p0 = hs[(long long)s0 * 8 + sub];
        uint4 p1 = hs[(long long)s1 * 8 + sub];
        __half2 t0 = __hadd2(*(__half2*)&p0.x, *(__half2*)&p1.x);
        __half2 t1 = __hadd2(*(__half2*)&p0.y, *(__half2*)&p1.y);
        __half2 t2 = __hadd2(*(__half2*)&p0.z, *(__half2*)&p1.z);
        __half2 t3 = __hadd2(*(__half2*)&p0.w, *(__half2*)&p1.w);
        float2 f;
        f = __half22float2(t0); acc[0] += f.x; acc[1] += f.y;
        f = __half22float2(t1); acc[2] += f.x; acc[3] += f.y;
        f = __half22float2(t2); acc[4] += f.x; acc[5] += f.y;
        f = __half22float2(t3); acc[6] += f.x; acc[7] += f.y;
    }
    // tail: up to 7 edges, 4 at a time, predicated per group
    for (; i < end; i += 4) {
        int idx = i + g;
        if (idx < end) {
            int s = __ldg(&g_csrc[idx]);
            uint4 p = hs[(long long)s * 8 + sub];
            float2 f;
            f = __half22float2(*(__half2*)&p.x); acc[0] += f.x; acc[1] += f.y;
            f = __half22float2(*(__half2*)&p.y); acc[2] += f.x; acc[3] += f.y;
            f = __half22float2(*(__half2*)&p.z); acc[4] += f.x; acc[5] += f.y;
            f = __half22float2(*(__half2*)&p.w); acc[6] += f.x; acc[7] += f.y;
        }
    }

    // combine the 4 edge-groups (lanes sharing the same sub)
#pragma unroll
    for (int k = 0; k < 8; k++) {
        acc[k] += __shfl_xor_sync(0xFFFFFFFFu, acc[k], 8);
        acc[k] += __shfl_xor_sync(0xFFFFFFFFu, acc[k], 16);
    }

    // add self-loop term (post-butterfly so it is counted once)
    {
        float2 f;
        f = __half22float2(*(__half2*)&self.x); acc[0] += f.x; acc[1] += f.y;
        f = __half22float2(*(__half2*)&self.y); acc[2] += f.x; acc[3] += f.y;
        f = __half22float2(*(__half2*)&self.z); acc[4] += f.x; acc[5] += f.y;
        f = __half22float2(*(__half2*)&self.w); acc[6] += f.x; acc[7] += f.y;
    }

    // epilogue + store: groups 0 and 1 each write one float4
    if (g < 2) {
        float4 bv = ((const float4*)b)[sub * 2 + g];
        int k0 = g * 4;
        float4 o;
        o.x = bv.x + di * acc[k0 + 0];
        o.y = bv.y + di * acc[k0 + 1];
        o.z = bv.z + di * acc[k0 + 2];
        o.w = bv.w + di * acc[k0 + 3];
        ((float4*)y)[(long long)w * 16 + sub * 2 + g] = o;
    }
}

// ------------------------------------------------------------------
// K_pool v2: segment mean accumulation. CHUNK=32 nodes/block,
//   4-wide unrolled loads for MLP. batch sorted -> register-accumulate,
//   flush on graph change. 64 threads/block (thread = dim).
// ------------------------------------------------------------------
#define POOL_CHUNK 32

#define POOL_STEP(bg, v)                                    \
    do {                                                    \
        if ((bg) != cur) {                                  \
            if (cur >= 0) {                                 \
                atomicAdd(&g_pool[cur * D + d], acc);       \
                if (d == 0) atomicAdd(&g_cnt[cur], cnt);    \
            }                                               \
            cur = (bg); acc = 0.f; cnt = 0.f;               \
        }                                                   \
        acc += (v); cnt += 1.f;                             \
    } while (0)

__global__ void k_pool(const float* __restrict__ x, const int* __restrict__ batch, int N) {
    int d = threadIdx.x;              // 0..63
    int s = blockIdx.x * POOL_CHUNK;
    int eN = min(s + POOL_CHUNK, N);
    float acc = 0.0f, cnt = 0.0f;
    int cur = -1;
    int n = s;
    for (; n + 4 <= eN; n += 4) {
        int b0 = batch[n],     b1 = batch[n + 1];
        int b2 = batch[n + 2], b3 = batch[n + 3];
        float v0 = x[(long long)n * D + d];
        float v1 = x[(long long)(n + 1) * D + d];
        float v2 = x[(long long)(n + 2) * D + d];
        float v3 = x[(long long)(n + 3) * D + d];
        POOL_STEP(b0, v0);
        POOL_STEP(b1, v1);
        POOL_STEP(b2, v2);
        POOL_STEP(b3, v3);
    }
    for (; n < eN; n++) {
        int bg = batch[n];
        float v = x[(long long)n * D + d];
        POOL_STEP(bg, v);
    }
    if (cur >= 0) {
        atomicAdd(&g_pool[cur * D + d], acc);
        if (d == 0) atomicAdd(&g_cnt[cur], cnt);
    }
}

// ------------------------------------------------------------------
// K_final: pooled = sum/max(cnt,1); out = pooled / ||pooled||_2
// ------------------------------------------------------------------
__global__ void k_final(float* __restrict__ out) {
    int r    = blockIdx.x * 32 + (threadIdx.x >> 5);
    int lane = threadIdx.x & 31;
    float c  = fmaxf(g_cnt[r], 1.0f);
    float v0 = g_pool[r * D + lane]      / c;
    float v1 = g_pool[r * D + 32 + lane] / c;
    float ss = v0 * v0 + v1 * v1;
#pragma unroll
    for (int o = 16; o > 0; o >>= 1) ss += __shfl_xor_sync(0xFFFFFFFFu, ss, o);
    float inv = rsqrtf(ss);
    out[r * D + lane]      = v0 * inv;
    out[r * D + 32 + lane] = v1 * inv;
}

// ------------------------------------------------------------------
// Host launcher
// ------------------------------------------------------------------
extern "C" void kernel_launch(void* const* d_in, const int* in_sizes, int n_in,
                              void* d_out, int out_size) {
    const int*   node_types = (const int*)  d_in[0];
    const int*   edge_index = (const int*)  d_in[1];
    const int*   batch      = (const int*)  d_in[2];
    const float* emb_table  = (const float*)d_in[3];
    const float* W1 = (const float*)d_in[4];
    const float* b1 = (const float*)d_in[5];
    const float* W2 = (const float*)d_in[6];
    const float* b2 = (const float*)d_in[7];
    const float* W3 = (const float*)d_in[8];
    const float* b3 = (const float*)d_in[9];
    float* out = (float*)d_out;

    const int N = in_sizes[0];
    const int E = in_sizes[1] / 2;
    const int V = in_sizes[3] / D;
    const int* row = edge_index;        // edge_index[0, :]
    const int* col = edge_index + E;    // edge_index[1, :]

    float* bufA; cudaGetSymbolAddress((void**)&bufA, g_bufA);
    uint4* hsB;  cudaGetSymbolAddress((void**)&hsB,  g_hs);
    float* bufC; cudaGetSymbolAddress((void**)&bufC, g_bufC);
    int*   degi; cudaGetSymbolAddress((void**)&degi, g_degi);
    float* pool; cudaGetSymbolAddress((void**)&pool, g_pool);
    float* cnt;  cudaGetSymbolAddress((void**)&cnt,  g_cnt);

    const int T = 256;
    const int scanB = (N + 1023) / 1024;

    cudaMemsetAsync(degi, 0, N * sizeof(int));
    cudaMemsetAsync(pool, 0, G * D * sizeof(float));
    cudaMemsetAsync(cnt,  0, G * sizeof(float));

    int mm_blocks  = (N + 127) / 128;
    int agg_blocks = (N + 7) / 8;       // 8 warps/block, warp per node

    // ---- precompute + layer-1 table path (k_hs1 sits at kernel slot 4 -> ncu)
    k_htab <<<V, 64>>>(emb_table, W1);                                    // 1
    k_hist <<<(E + T - 1) / T, T>>>(col, E);                              // 2
    k_scan1<<<scanB, 256>>>(N);                                           // 3
    k_hs1  <<<(N * 16 + T - 1) / T, T>>>(node_types, (uint2*)hsB, N);     // 4 <- profiled
    k_scan2<<<1, 256>>>(scanB);                                           // 5
    k_scan3<<<(N + T - 1) / T, T>>>(N, E);                                // 6
    k_build<<<(E + T - 1) / T, T>>>(row, col, E);                         // 7

    // layer 1 aggregation
    k_agg<<<agg_blocks, T>>>(hsB, b1, bufC, N);
    // layer 2
    k_mm <<<mm_blocks, T>>>(bufC, W2, (uint2*)hsB, N, 1);
    k_agg<<<agg_blocks, T>>>(hsB, b2, bufA, N);
    // layer 3
    k_mm <<<mm_blocks, T>>>(bufA, W3, (uint2*)hsB, N, 1);
    k_agg<<<agg_blocks, T>>>(hsB, b3, bufC, N);

    // mean-pool + L2 normalize
    k_pool <<<(N + POOL_CHUNK - 1) / POOL_CHUNK, 64>>>(bufC, batch, N);
    k_final<<<2, 1024>>>(out);
}